// round 11
// baseline (speedup 1.0000x reference)
#include <cuda_runtime.h>
#include <cuda_fp16.h>
#include <math_constants.h>

// GATv2 additive attention + masked softmax, mask-compacted v7.
// fp16 q,k in smem (0.5-scaled); u = hadd2(q,k); tanh.approx.f16x2 (2 elem/MUFU);
// silu + a-weighted accumulation in fp32. K rows: 144B stride (conflict-tamed gather).
// score(b,h,i,j) = sum_d a[h,d] * silu(q+k);  silu(s)=u*(1+tanh(u)), u=s/2.

#define B_   2
#define H_   8
#define LQ_  384
#define LK_  384
#define D_   64
#define ROWS 8            // q rows per block, 1 warp per row
#define NC   12           // LK/32 chunks
#define KSTR 144          // K smem row stride in BYTES (row data = 128B fp16)

__device__ __forceinline__ __half2 tanh2_approx(__half2 x) {
    unsigned r, xi = *reinterpret_cast<unsigned*>(&x);
    asm("tanh.approx.f16x2 %0, %1;" : "=r"(r) : "r"(xi));
    return *reinterpret_cast<__half2*>(&r);
}

__global__ __launch_bounds__(256, 2)
void gatv2_kernel(const float* __restrict__ q, const float* __restrict__ k,
                  const float* __restrict__ att, const int* __restrict__ mask,
                  float* __restrict__ out)
{
    extern __shared__ float smem[];
    // layout: K fp16 [LK][KSTR B] | q fp16 [ROWS][64] | a fp32 [D] | idx16 [ROWS][LK]
    char*  ksb = (char*)smem;
    char*  qsb = ksb + LK_ * KSTR;                     // 8 rows * 128B
    float* as  = (float*)(qsb + ROWS * 128);           // [D]
    unsigned short* idxb = (unsigned short*)(as + D_); // [ROWS][LK]

    const int ntiles = LQ_ / ROWS;       // 48
    int blk   = blockIdx.x;
    int bh    = blk / ntiles;
    int itile = blk - bh * ntiles;
    int h     = bh & (H_ - 1);
    int tid   = threadIdx.x;
    int warp  = tid >> 5, lane = tid & 31;
    int i     = itile * ROWS + warp;

    // ---- stage 0.5*K as fp16 (144B stride) ----
    const float4* kg = (const float4*)(k + (size_t)bh * LK_ * D_);
    for (int idxr = tid; idxr < LK_ * D_ / 4; idxr += 256) {
        int j = idxr >> 4, d4 = idxr & 15;
        float4 v = kg[idxr];
        uint2 w;
        *reinterpret_cast<__half2*>(&w.x) = __floats2half2_rn(0.5f * v.x, 0.5f * v.y);
        *reinterpret_cast<__half2*>(&w.y) = __floats2half2_rn(0.5f * v.z, 0.5f * v.w);
        *reinterpret_cast<uint2*>(ksb + j * KSTR + d4 * 8) = w;
    }
    // ---- stage 0.5*q as fp16 (128B rows, broadcast-only) ----
    const float4* qg = (const float4*)(q + ((size_t)bh * LQ_ + itile * ROWS) * D_);
    for (int idxr = tid; idxr < ROWS * D_ / 4; idxr += 256) {
        int r = idxr >> 4, d4 = idxr & 15;
        float4 v = qg[idxr];
        uint2 w;
        *reinterpret_cast<__half2*>(&w.x) = __floats2half2_rn(0.5f * v.x, 0.5f * v.y);
        *reinterpret_cast<__half2*>(&w.y) = __floats2half2_rn(0.5f * v.z, 0.5f * v.w);
        *reinterpret_cast<uint2*>(qsb + r * 128 + d4 * 8) = w;
    }
    if (tid < D_) as[tid] = att[h * D_ + tid];

    // ---- mask ballot + compaction scatter (warp-private stripe) ----
    const int* mrow = mask + ((size_t)bh * LQ_ + i) * LK_;
    unsigned short* stripe = idxb + warp * LK_;
    int base = 0;
#pragma unroll
    for (int c = 0; c < NC; c++) {
        int j = c * 32 + lane;
        int keep = (mrow[j] == 0);
        unsigned b = __ballot_sync(0xffffffffu, keep);
        if (keep) stripe[base + __popc(b & ((1u << lane) - 1u))] = (unsigned short)j;
        base += __popc(b);
    }
    int nkeep  = base;
    int nchunk = (nkeep + 31) >> 5;

    __syncthreads();

    // ---- compacted indices to registers ----
    int jdx[NC];
#pragma unroll
    for (int cc = 0; cc < NC; cc++) {
        int slot = cc * 32 + lane;
        jdx[cc] = (slot < nkeep) ? (int)stripe[slot] : 0;
    }

    const uint4* qrow4 = (const uint4*)(qsb + warp * 128);   // 8 x uint4 (8 halfs each)
    float acc[NC];
#pragma unroll
    for (int cc = 0; cc < NC; cc++) acc[cc] = -CUDART_INF_F;

    // helper macro: 2 elems of one row-chain via hadd2 + tanh.f16x2 + fp32 silu
#define PAIR2(Sa, Sb, QH2, KH2, AX, AY)                                         \
    {                                                                           \
        __half2 u2 = __hadd2(QH2, KH2);                                         \
        __half2 t2 = tanh2_approx(u2);                                          \
        float2 uf = __half22float2(u2);                                         \
        float2 tf = __half22float2(t2);                                         \
        Sa = fmaf(AX, fmaf(uf.x, tf.x, uf.x), Sa);                              \
        Sb = fmaf(AY, fmaf(uf.y, tf.y, uf.y), Sb);                              \
    }

    // ---- chunk-pair score loop ----
#pragma unroll
    for (int p = 0; p < NC / 2; p++) {
        if (2 * p < nchunk) {
            const uint4* kr0 = (const uint4*)(ksb + jdx[2 * p]     * KSTR);
            const uint4* kr1 = (const uint4*)(ksb + jdx[2 * p + 1] * KSTR);
            float s0 = 0.f, s1 = 0.f, s2 = 0.f, s3 = 0.f;
            float s4 = 0.f, s5 = 0.f, s6 = 0.f, s7 = 0.f;
#pragma unroll 2
            for (int c8 = 0; c8 < 8; c8++) {       // 8 d-values per iter
                uint4 qa = qrow4[c8];
                uint4 ka = kr0[c8];
                uint4 kb = kr1[c8];
                float4 aa = *(const float4*)(as + 8 * c8);
                float4 ab = *(const float4*)(as + 8 * c8 + 4);
                __half2 qh;
                qh = *reinterpret_cast<__half2*>(&qa.x);
                PAIR2(s0, s1, qh, *reinterpret_cast<__half2*>(&ka.x), aa.x, aa.y);
                PAIR2(s4, s5, qh, *reinterpret_cast<__half2*>(&kb.x), aa.x, aa.y);
                qh = *reinterpret_cast<__half2*>(&qa.y);
                PAIR2(s2, s3, qh, *reinterpret_cast<__half2*>(&ka.y), aa.z, aa.w);
                PAIR2(s6, s7, qh, *reinterpret_cast<__half2*>(&kb.y), aa.z, aa.w);
                qh = *reinterpret_cast<__half2*>(&qa.z);
                PAIR2(s0, s1, qh, *reinterpret_cast<__half2*>(&ka.z), ab.x, ab.y);
                PAIR2(s4, s5, qh, *reinterpret_cast<__half2*>(&kb.z), ab.x, ab.y);
                qh = *reinterpret_cast<__half2*>(&qa.w);
                PAIR2(s2, s3, qh, *reinterpret_cast<__half2*>(&ka.w), ab.z, ab.w);
                PAIR2(s6, s7, qh, *reinterpret_cast<__half2*>(&kb.w), ab.z, ab.w);
            }
            acc[2 * p]     = ((2 * p)     * 32 + lane < nkeep) ? ((s0 + s1) + (s2 + s3)) : -CUDART_INF_F;
            acc[2 * p + 1] = ((2 * p + 1) * 32 + lane < nkeep) ? ((s4 + s5) + (s6 + s7)) : -CUDART_INF_F;
        }
    }
#undef PAIR2

    // ---- softmax over compacted values ----
    float mx = -CUDART_INF_F;
#pragma unroll
    for (int cc = 0; cc < NC; cc++) mx = fmaxf(mx, acc[cc]);
#pragma unroll
    for (int o = 16; o; o >>= 1) mx = fmaxf(mx, __shfl_xor_sync(0xffffffffu, mx, o));

    float sum = 0.f;
#pragma unroll
    for (int cc = 0; cc < NC; cc++) {
        float e = __expf(acc[cc] - mx);
        acc[cc] = e;
        sum += e;
    }
#pragma unroll
    for (int o = 16; o; o >>= 1) sum += __shfl_xor_sync(0xffffffffu, sum, o);
    float inv = (sum > 0.f) ? __fdividef(1.f, sum) : 0.f;

    // ---- scatter via smem (reuse K region after barrier), dense store ----
    __syncthreads();
    float* ws = (float*)ksb + warp * LK_;
#pragma unroll
    for (int c = 0; c < NC; c++) ws[c * 32 + lane] = 0.f;
    __syncwarp();
#pragma unroll
    for (int cc = 0; cc < NC; cc++) {
        if (cc * 32 + lane < nkeep) ws[jdx[cc]] = acc[cc] * inv;
    }
    __syncwarp();

    float* orow = out + ((size_t)bh * LQ_ + i) * LK_;
#pragma unroll
    for (int c = 0; c < NC; c++) orow[c * 32 + lane] = ws[c * 32 + lane];
}

extern "C" void kernel_launch(void* const* d_in, const int* in_sizes, int n_in,
                              void* d_out, int out_size)
{
    const float* q   = (const float*)d_in[0];
    const float* k   = (const float*)d_in[1];
    const float* att = (const float*)d_in[2];
    const int*   m   = (const int*)d_in[3];
    float* out       = (float*)d_out;

    // K 384*144 = 55296 + q 8*128 = 1024 + a 256 + idx16 6144 = 62,720 B
    const int smem_bytes = LK_ * KSTR + ROWS * 128 + D_ * (int)sizeof(float)
                         + ROWS * LK_ * (int)sizeof(unsigned short);
    cudaFuncSetAttribute(gatv2_kernel, cudaFuncAttributeMaxDynamicSharedMemorySize, smem_bytes);

    dim3 grid(B_ * H_ * (LQ_ / ROWS));   // 768
    gatv2_kernel<<<grid, 256, smem_bytes>>>(q, k, att, m, out);
}

// round 12
// speedup vs baseline: 1.0518x; 1.0518x over previous
#include <cuda_runtime.h>
#include <cuda_fp16.h>
#include <math_constants.h>

// GATv2 additive attention + masked softmax, v8.
// - fp16 q,k,a in smem (q,k pre-scaled 0.5); silu + a-product entirely in fp16
//   (HADD2 + tanh.approx.f16x2 + 2x HFMA2), flushed to fp32 every 8 d-values
//   (mini fp16 chains of 2 adds) -> F2F conversions 0.5/elem instead of 2/elem.
// - class-interleaved compaction: slot = (j&7) + 8*class_rank -> every 32-slot
//   chunk has exactly 4 indices per bank-class -> gather LDS.128 at 4-phase floor.
// score(b,h,i,j) = sum_d a[h,d]*silu(q+k); silu(s)=u*(1+tanh(u)), u=s/2.

#define B_   2
#define H_   8
#define LQ_  384
#define LK_  384
#define D_   64
#define ROWS 8            // q rows per block, 1 warp per row
#define NC   12           // LK/32 chunks
#define KSTR 144          // K smem row stride in BYTES (row data = 128B fp16)
#define INVALID16 0xFFFFu

__device__ __forceinline__ __half2 tanh2_approx(__half2 x) {
    unsigned r, xi = *reinterpret_cast<unsigned*>(&x);
    asm("tanh.approx.f16x2 %0, %1;" : "=r"(r) : "r"(xi));
    return *reinterpret_cast<__half2*>(&r);
}
#define H2(u) (*reinterpret_cast<const __half2*>(&(u)))

__global__ __launch_bounds__(256, 2)
void gatv2_kernel(const float* __restrict__ q, const float* __restrict__ k,
                  const float* __restrict__ att, const int* __restrict__ mask,
                  float* __restrict__ out)
{
    extern __shared__ float smem[];
    // layout: K fp16 [LK][KSTR B] | q fp16 [ROWS][128B] | a fp16 [128B] | idx16 [ROWS][LK]
    char*  ksb = (char*)smem;
    char*  qsb = ksb + LK_ * KSTR;                       // 8 * 128B
    char*  asb = qsb + ROWS * 128;                       // 64 halfs = 128B
    unsigned short* idxb = (unsigned short*)(asb + 128); // [ROWS][LK]

    const int ntiles = LQ_ / ROWS;       // 48
    int blk   = blockIdx.x;
    int bh    = blk / ntiles;
    int itile = blk - bh * ntiles;
    int h     = bh & (H_ - 1);
    int tid   = threadIdx.x;
    int warp  = tid >> 5, lane = tid & 31;
    int i     = itile * ROWS + warp;

    // ---- stage 0.5*K as fp16 (144B stride) ----
    const float4* kg = (const float4*)(k + (size_t)bh * LK_ * D_);
    for (int idxr = tid; idxr < LK_ * D_ / 4; idxr += 256) {
        int j = idxr >> 4, d4 = idxr & 15;
        float4 v = kg[idxr];
        uint2 w;
        *reinterpret_cast<__half2*>(&w.x) = __floats2half2_rn(0.5f * v.x, 0.5f * v.y);
        *reinterpret_cast<__half2*>(&w.y) = __floats2half2_rn(0.5f * v.z, 0.5f * v.w);
        *reinterpret_cast<uint2*>(ksb + j * KSTR + d4 * 8) = w;
    }
    // ---- stage 0.5*q as fp16 (128B rows) ----
    const float4* qg = (const float4*)(q + ((size_t)bh * LQ_ + itile * ROWS) * D_);
    for (int idxr = tid; idxr < ROWS * D_ / 4; idxr += 256) {
        int r = idxr >> 4, d4 = idxr & 15;
        float4 v = qg[idxr];
        uint2 w;
        *reinterpret_cast<__half2*>(&w.x) = __floats2half2_rn(0.5f * v.x, 0.5f * v.y);
        *reinterpret_cast<__half2*>(&w.y) = __floats2half2_rn(0.5f * v.z, 0.5f * v.w);
        *reinterpret_cast<uint2*>(qsb + r * 128 + d4 * 8) = w;
    }
    // ---- stage a as fp16 ----
    if (tid < 32) {
        __half2 a2 = __floats2half2_rn(att[h * D_ + 2 * tid], att[h * D_ + 2 * tid + 1]);
        reinterpret_cast<__half2*>(asb)[tid] = a2;
    }

    // ---- class-interleaved compaction (warp-private stripe) ----
    unsigned short* stripe = idxb + warp * LK_;
    // prefill with INVALID16
    {
        unsigned* sw = (unsigned*)stripe;
#pragma unroll
        for (int r = 0; r < 6; r++) sw[lane + 32 * r] = 0xFFFFFFFFu;
    }
    __syncwarp();

    const int* mrow = mask + ((size_t)bh * LQ_ + i) * LK_;
    unsigned km = 0;                       // per-lane 12-bit keep mask
#pragma unroll
    for (int c = 0; c < NC; c++)
        if (mrow[c * 32 + lane] == 0) km |= (1u << c);
    int cnt = __popc(km);

    // prefix of counts among lanes of my class (lane&7), lanes below me
    int c8  = __shfl_up_sync(0xffffffffu, cnt, 8);
    int c16 = __shfl_up_sync(0xffffffffu, cnt, 16);
    int c24 = __shfl_up_sync(0xffffffffu, cnt, 24);
    int p = (lane >= 8 ? c8 : 0) + (lane >= 16 ? c16 : 0) + (lane >= 24 ? c24 : 0);

    // write my kept j's at slot = (lane&7) + 8*(p + r)
    {
        int r = 0;
        unsigned m = km;
#pragma unroll
        for (int c = 0; c < NC; c++) {
            if (m & 1u) { stripe[(lane & 7) + 8 * (p + r)] = (unsigned short)(c * 32 + lane); r++; }
            m >>= 1;
        }
    }
    // Nmax = max class total
    int tot = p + cnt;                                    // at lane 24+c: total of class c
    int y = __shfl_sync(0xffffffffu, tot, 24 + (lane & 7));
    int nmax = y;
#pragma unroll
    for (int o = 1; o <= 4; o <<= 1) nmax = max(nmax, __shfl_xor_sync(0xffffffffu, nmax, o));
    int nchunk = (nmax + 3) >> 2;                         // ceil(8*Nmax/32)

    __syncthreads();                                      // staging + stripes visible

    // ---- compacted indices + validity to registers ----
    int jdx[NC];
    unsigned vmask = 0;
#pragma unroll
    for (int cc = 0; cc < NC; cc++) {
        unsigned short v = stripe[cc * 32 + lane];
        int valid = (v != (unsigned short)INVALID16);
        jdx[cc] = valid ? (int)v : 0;
        vmask |= ((unsigned)valid) << cc;
    }

    const uint4* qrow4 = (const uint4*)(qsb + warp * 128);
    const uint4* arow4 = (const uint4*)asb;
    float acc[NC];
#pragma unroll
    for (int cc = 0; cc < NC; cc++) acc[cc] = -CUDART_INF_F;

    __half2 hz = __floats2half2_rn(0.f, 0.f);

    // one half2 step: hacc += a2 * (u2*(1+tanh(u2)))
#define STEP(HACC, QW, KW, AW)                                         \
    {                                                                  \
        __half2 u2 = __hadd2(H2(QW), H2(KW));                          \
        __half2 t2 = tanh2_approx(u2);                                 \
        __half2 sl = __hfma2(u2, t2, u2);                              \
        HACC = __hfma2(H2(AW), sl, HACC);                              \
    }

    // ---- chunk-pair score loop ----
#pragma unroll
    for (int pp = 0; pp < NC / 2; pp++) {
        if (2 * pp < nchunk) {
            const uint4* kr0 = (const uint4*)(ksb + jdx[2 * pp]     * KSTR);
            const uint4* kr1 = (const uint4*)(ksb + jdx[2 * pp + 1] * KSTR);
            float sA0 = 0.f, sA1 = 0.f, sB0 = 0.f, sB1 = 0.f;
#pragma unroll
            for (int cI = 0; cI < 8; cI++) {             // 8 d-values per iter
                uint4 qa = qrow4[cI];
                uint4 aw = arow4[cI];
                uint4 ka = kr0[cI];
                uint4 kb = kr1[cI];
                __half2 hA01 = hz, hA23 = hz, hB01 = hz, hB23 = hz;
                STEP(hA01, qa.x, ka.x, aw.x); STEP(hA01, qa.y, ka.y, aw.y);
                STEP(hA23, qa.z, ka.z, aw.z); STEP(hA23, qa.w, ka.w, aw.w);
                STEP(hB01, qa.x, kb.x, aw.x); STEP(hB01, qa.y, kb.y, aw.y);
                STEP(hB23, qa.z, kb.z, aw.z); STEP(hB23, qa.w, kb.w, aw.w);
                float2 f;
                f = __half22float2(hA01); sA0 += f.x; sA0 += f.y;
                f = __half22float2(hA23); sA1 += f.x; sA1 += f.y;
                f = __half22float2(hB01); sB0 += f.x; sB0 += f.y;
                f = __half22float2(hB23); sB1 += f.x; sB1 += f.y;
            }
            acc[2 * pp]     = ((vmask >> (2 * pp))     & 1u) ? (sA0 + sA1) : -CUDART_INF_F;
            acc[2 * pp + 1] = ((vmask >> (2 * pp + 1)) & 1u) ? (sB0 + sB1) : -CUDART_INF_F;
        }
    }
#undef STEP

    // ---- softmax over compacted values ----
    float mx = -CUDART_INF_F;
#pragma unroll
    for (int cc = 0; cc < NC; cc++) mx = fmaxf(mx, acc[cc]);
#pragma unroll
    for (int o = 16; o; o >>= 1) mx = fmaxf(mx, __shfl_xor_sync(0xffffffffu, mx, o));

    float sum = 0.f;
#pragma unroll
    for (int cc = 0; cc < NC; cc++) {
        float e = __expf(acc[cc] - mx);
        acc[cc] = e;
        sum += e;
    }
#pragma unroll
    for (int o = 16; o; o >>= 1) sum += __shfl_xor_sync(0xffffffffu, sum, o);
    float inv = (sum > 0.f) ? __fdividef(1.f, sum) : 0.f;

    // ---- scatter via smem (reuse K region after barrier), dense store ----
    __syncthreads();
    float* ws = (float*)ksb + warp * LK_;
#pragma unroll
    for (int c = 0; c < NC; c++) ws[c * 32 + lane] = 0.f;
    __syncwarp();
#pragma unroll
    for (int cc = 0; cc < NC; cc++) {
        if ((vmask >> cc) & 1u) ws[jdx[cc]] = acc[cc] * inv;
    }
    __syncwarp();

    float* orow = out + ((size_t)bh * LQ_ + i) * LK_;
#pragma unroll
    for (int c = 0; c < NC; c++) orow[c * 32 + lane] = ws[c * 32 + lane];
}

extern "C" void kernel_launch(void* const* d_in, const int* in_sizes, int n_in,
                              void* d_out, int out_size)
{
    const float* q   = (const float*)d_in[0];
    const float* k   = (const float*)d_in[1];
    const float* att = (const float*)d_in[2];
    const int*   m   = (const int*)d_in[3];
    float* out       = (float*)d_out;

    // K 55296 + q 1024 + a 128 + idx16 6144 = 62,592 B
    const int smem_bytes = LK_ * KSTR + ROWS * 128 + 128
                         + ROWS * LK_ * (int)sizeof(unsigned short);
    cudaFuncSetAttribute(gatv2_kernel, cudaFuncAttributeMaxDynamicSharedMemorySize, smem_bytes);

    dim3 grid(B_ * H_ * (LQ_ / ROWS));   // 768
    gatv2_kernel<<<grid, 256, smem_bytes>>>(q, k, att, m, out);
}